// round 1
// baseline (speedup 1.0000x reference)
#include <cuda_runtime.h>
#include <cstdint>

#define NEG_CLAMP -20.0f
#define EPSV 1e-6f

static constexpr int Bb = 8, Ll = 4096, Hh = 16, Ee = 64;
static constexpr int BH = Bb * Hh;        // 128
static constexpr int RS = Hh * Ee;        // row stride in floats = 1024
static constexpr int SPLIT = 8;
static constexpr int ROWS1 = Ll / SPLIT;  // 512 rows per pass-1 block
static constexpr int TILE1 = 64;

// scratch (static device arrays: allowed; runtime alloc is not)
__device__ float g_kv_part[SPLIT * BH * Ee * Ee];
__device__ float g_ks_part[SPLIT * BH * Ee];
__device__ float g_kv[BH * Ee * Ee];
__device__ float g_ks[BH * Ee];

typedef unsigned long long u64;

__device__ __forceinline__ u64 pack2(float x, float y) {
    u64 r; asm("mov.b64 %0, {%1, %2};" : "=l"(r) : "f"(x), "f"(y)); return r;
}
__device__ __forceinline__ float2 unpack2(u64 v) {
    float2 r; asm("mov.b64 {%0, %1}, %2;" : "=f"(r.x), "=f"(r.y) : "l"(v)); return r;
}
// Blackwell packed fp32 FMA (2 FMAs/instr -> 128 FMA/SM/cyc vs 64 for FFMA-3reg)
__device__ __forceinline__ u64 ffma2(u64 a, u64 b, u64 c) {
    u64 d; asm("fma.rn.f32x2 %0, %1, %2, %3;" : "=l"(d) : "l"(a), "l"(b), "l"(c)); return d;
}
__device__ __forceinline__ u64 fmul2(u64 a, u64 b) {
    u64 d; asm("mul.rn.f32x2 %0, %1, %2;" : "=l"(d) : "l"(a), "l"(b)); return d;
}

// Permuted layout for rows of 64 duplicated 8-byte pairs (32 x 16B units per row).
// unit u (0..31) placed at 16B slot (u&3)*8 + (u>>2), so a warp whose lanes index
// consecutive "groups of 4 units" reads 128B-contiguous, conflict-free.
// Returns offset of pair p (0..63) in 8-byte units within the 512B row.
__device__ __forceinline__ int dup_off8(int p) {
    int u = p >> 1, h = p & 1;
    return ((((u & 3) << 3) + (u >> 2)) << 1) + h;
}

__device__ __forceinline__ float warp_sum(float v) {
    #pragma unroll
    for (int o = 16; o > 0; o >>= 1) v += __shfl_xor_sync(0xffffffffu, v, o);
    return v;
}

// ---------------------------------------------------------------------------
// Pass 1: per (head, L-split): KV_partial = phi(K)^T V  (64x64), ksum_partial
// ---------------------------------------------------------------------------
__global__ void __launch_bounds__(256) k_pass1(const float* __restrict__ Kin,
                                               const float* __restrict__ Vin,
                                               const float* __restrict__ D1) {
    __shared__ __align__(16) float s_kd[TILE1 * 128]; // dup phi(k): 64 rows x 512B = 32KB
    __shared__ __align__(16) float s_v[TILE1 * 64];   // v tile: 16KB (permuted units)

    const int bh = blockIdx.x / SPLIT, sp = blockIdx.x % SPLIT;
    const int b = bh >> 4, h = bh & 15;
    const int tid = threadIdx.x, w = tid >> 5, lane = tid & 31;
    const int g = tid >> 6, t = tid & 63, eg = t >> 3, dg = t & 7;

    const float invT = 1.0f / log1pf(__expf(*D1));
    const long base = (long)b * Ll * RS + h * Ee;

    u64 acc[8][4]; // e (8) x d-pair (4) register tile, group covers 64x64
    #pragma unroll
    for (int i = 0; i < 8; i++)
        #pragma unroll
        for (int j = 0; j < 4; j++) acc[i][j] = 0ull;
    float ks0 = 0.f, ks1 = 0.f;

    const int l00 = sp * ROWS1;
    for (int tile = 0; tile < ROWS1 / TILE1; tile++) {
        const int l0 = l00 + tile * TILE1;

        // stage V tile with permuted 16B units
        #pragma unroll
        for (int i = 0; i < 4; i++) {
            int lin = tid + 256 * i;
            int r = lin >> 4, q = lin & 15;
            float4 vv = *(const float4*)(Vin + base + (long)(l0 + r) * RS + q * 4);
            int off16 = ((q & 1) << 3) + (q >> 1);
            *(float4*)(s_v + r * 64 + off16 * 4) = vv;
        }
        // softmax(K) rows -> duplicated pairs. warp w handles rows w, w+8, ...
        #pragma unroll
        for (int i = 0; i < 8; i++) {
            int r = w + 8 * i;
            const float* kp = Kin + base + (long)(l0 + r) * RS;
            float x0 = kp[lane], x1 = kp[lane + 32];
            x0 = x0 < 0.f ? NEG_CLAMP : x0;
            x1 = x1 < 0.f ? NEG_CLAMP : x1;
            float e0 = __expf(x0 * invT), e1 = __expf(x1 * invT);
            float rs = 1.0f / warp_sum(e0 + e1);
            e0 *= rs; e1 *= rs;
            ks0 += e0; ks1 += e1;
            *(u64*)(s_kd + r * 128 + dup_off8(lane) * 2)      = pack2(e0, e0);
            *(u64*)(s_kd + r * 128 + dup_off8(lane + 32) * 2) = pack2(e1, e1);
        }
        __syncthreads();

        // rank-1 update accumulation: group g handles rows 16g..16g+15
        #pragma unroll 1
        for (int rr = 0; rr < 16; rr++) {
            const float* kr = s_kd + (g * 16 + rr) * 128;
            const float* vr = s_v  + (g * 16 + rr) * 64;
            ulonglong2 kd0 = *(const ulonglong2*)(kr + (0 * 8 + eg) * 4);
            ulonglong2 kd1 = *(const ulonglong2*)(kr + (1 * 8 + eg) * 4);
            ulonglong2 kd2 = *(const ulonglong2*)(kr + (2 * 8 + eg) * 4);
            ulonglong2 kd3 = *(const ulonglong2*)(kr + (3 * 8 + eg) * 4);
            u64 kk[8] = {kd0.x, kd0.y, kd1.x, kd1.y, kd2.x, kd2.y, kd3.x, kd3.y};
            ulonglong2 vp0 = *(const ulonglong2*)(vr + (0 * 8 + dg) * 4);
            ulonglong2 vp1 = *(const ulonglong2*)(vr + (1 * 8 + dg) * 4);
            u64 vv2[4] = {vp0.x, vp0.y, vp1.x, vp1.y};
            #pragma unroll
            for (int e = 0; e < 8; e++)
                #pragma unroll
                for (int dp = 0; dp < 4; dp++)
                    acc[e][dp] = ffma2(kk[e], vv2[dp], acc[e][dp]);
        }
        __syncthreads();
    }

    // deterministic in-block reduction over the 4 groups (fixed order)
    float* KVsh = s_kd; // reuse, viewed as KV[64][64]
    for (int gg = 0; gg < 4; gg++) {
        if (g == gg) {
            #pragma unroll
            for (int e = 0; e < 8; e++)
                #pragma unroll
                for (int dp = 0; dp < 4; dp++) {
                    float2 a = unpack2(acc[e][dp]);
                    float* p = KVsh + (8 * eg + e) * 64 + 8 * dg + 2 * dp;
                    if (gg == 0) { p[0] = a.x;  p[1] = a.y; }
                    else         { p[0] += a.x; p[1] += a.y; }
                }
        }
        __syncthreads();
    }
    float* dst = g_kv_part + ((long)sp * BH + bh) * (Ee * Ee);
    #pragma unroll
    for (int i = 0; i < 4; i++) {
        int i4 = tid + 256 * i;
        *(float4*)(dst + i4 * 4) = *(const float4*)(KVsh + i4 * 4);
    }
    // ksum: per-warp registers -> shared -> partial
    float* kss = s_v; // reuse
    kss[w * 64 + lane] = ks0;
    kss[w * 64 + lane + 32] = ks1;
    __syncthreads();
    if (tid < 64) {
        float s = 0.f;
        #pragma unroll
        for (int ww = 0; ww < 8; ww++) s += kss[ww * 64 + tid];
        g_ks_part[((long)sp * BH + bh) * Ee + tid] = s;
    }
}

// ---------------------------------------------------------------------------
// Deterministic split reduction
// ---------------------------------------------------------------------------
__global__ void __launch_bounds__(256) k_reduce() {
    const int bh = blockIdx.x, tid = threadIdx.x;
    for (int i = tid; i < Ee * Ee; i += 256) {
        float s = 0.f;
        #pragma unroll
        for (int sp = 0; sp < SPLIT; sp++)
            s += g_kv_part[((long)sp * BH + bh) * (Ee * Ee) + i];
        g_kv[(long)bh * (Ee * Ee) + i] = s;
    }
    if (tid < Ee) {
        float s = 0.f;
        #pragma unroll
        for (int sp = 0; sp < SPLIT; sp++)
            s += g_ks_part[((long)sp * BH + bh) * Ee + tid];
        g_ks[(long)bh * Ee + tid] = s;
    }
}

// ---------------------------------------------------------------------------
// Pass 2: out_l = (phi(q_l) . KV) * z_l,  z_l = 1/(phi(q_l).ksum + eps)
// 4096 blocks, each: one head x 128 rows
// ---------------------------------------------------------------------------
__global__ void __launch_bounds__(256) k_pass2(const float* __restrict__ Qin,
                                               float* __restrict__ Out,
                                               const float* __restrict__ D1) {
    extern __shared__ __align__(16) float sm[];
    float* s_kv = sm;           // 8192 floats: KV duplicated pairs (permuted)
    float* s_qT = sm + 8192;    // 64*130: phi(q) transposed, stride 130
    float* s_z  = s_qT + 8320;  // 128
    float* s_ks = s_z + 128;    // 64

    const int bh = blockIdx.x >> 5, chunk = blockIdx.x & 31;
    const int b = bh >> 4, h = bh & 15;
    const int tid = threadIdx.x, w = tid >> 5, lane = tid & 31;
    const float invT = 1.0f / log1pf(__expf(*D1));
    const long base = (long)b * Ll * RS + h * Ee;
    const int l0 = chunk * 128;

    // stage duplicated KV
    const float* kvsrc = g_kv + (long)bh * (Ee * Ee);
    #pragma unroll
    for (int i = 0; i < 4; i++) {
        int i4 = tid + 256 * i;
        float4 v4 = *(const float4*)(kvsrc + i4 * 4);
        int e = i4 >> 4, q = i4 & 15;
        float* rowb = s_kv + e * 128;
        *(u64*)(rowb + dup_off8(q * 4 + 0) * 2) = pack2(v4.x, v4.x);
        *(u64*)(rowb + dup_off8(q * 4 + 1) * 2) = pack2(v4.y, v4.y);
        *(u64*)(rowb + dup_off8(q * 4 + 2) * 2) = pack2(v4.z, v4.z);
        *(u64*)(rowb + dup_off8(q * 4 + 3) * 2) = pack2(v4.w, v4.w);
    }
    if (tid < 64) s_ks[tid] = g_ks[(long)bh * Ee + tid];
    __syncthreads();

    // softmax(Q) -> transposed shared + z. warp w handles rows w, w+8, ...
    float ksA = s_ks[lane], ksB = s_ks[lane + 32];
    #pragma unroll
    for (int i = 0; i < 16; i++) {
        int r = w + 8 * i;
        const float* qp = Qin + base + (long)(l0 + r) * RS;
        float x0 = qp[lane], x1 = qp[lane + 32];
        x0 = x0 < 0.f ? NEG_CLAMP : x0;
        x1 = x1 < 0.f ? NEG_CLAMP : x1;
        float e0 = __expf(x0 * invT), e1 = __expf(x1 * invT);
        float rs = 1.0f / warp_sum(e0 + e1);
        e0 *= rs; e1 *= rs;
        s_qT[lane * 130 + r]        = e0;
        s_qT[(lane + 32) * 130 + r] = e1;
        float dot = warp_sum(e0 * ksA + e1 * ksB);
        if (lane == 0) s_z[r] = 1.0f / (dot + EPSV);
    }
    __syncthreads();

    // matmul: group g -> rows 32g..32g+31; thread: 4 rows (2 packed pairs) x 8 d
    const int g = tid >> 6, t = tid & 63, rg = t >> 3, dg = t & 7;
    const int rb = g * 32 + rg * 4;
    u64 acc[2][8];
    #pragma unroll
    for (int p = 0; p < 2; p++)
        #pragma unroll
        for (int j = 0; j < 8; j++) acc[p][j] = 0ull;

    #pragma unroll 4
    for (int e = 0; e < 64; e++) {
        const float* qc = s_qT + e * 130 + rb;
        u64 q0 = *(const u64*)qc;        // rows rb, rb+1
        u64 q1 = *(const u64*)(qc + 2);  // rows rb+2, rb+3
        const float* kr = s_kv + e * 128;
        ulonglong2 a0 = *(const ulonglong2*)(kr + (0 * 8 + dg) * 4);
        ulonglong2 a1 = *(const ulonglong2*)(kr + (1 * 8 + dg) * 4);
        ulonglong2 a2 = *(const ulonglong2*)(kr + (2 * 8 + dg) * 4);
        ulonglong2 a3 = *(const ulonglong2*)(kr + (3 * 8 + dg) * 4);
        u64 kv8[8] = {a0.x, a0.y, a1.x, a1.y, a2.x, a2.y, a3.x, a3.y};
        #pragma unroll
        for (int j = 0; j < 8; j++) {
            acc[0][j] = ffma2(q0, kv8[j], acc[0][j]);
            acc[1][j] = ffma2(q1, kv8[j], acc[1][j]);
        }
    }

    u64 zp[2];
    zp[0] = *(const u64*)(s_z + rb);
    zp[1] = *(const u64*)(s_z + rb + 2);
    #pragma unroll
    for (int p = 0; p < 2; p++) {
        float2 r2[8];
        #pragma unroll
        for (int j = 0; j < 8; j++) r2[j] = unpack2(fmul2(acc[p][j], zp[p]));
        float* o = Out + base + (long)(l0 + rb + 2 * p) * RS + 8 * dg;
        float4 f;
        f.x = r2[0].x; f.y = r2[1].x; f.z = r2[2].x; f.w = r2[3].x; *(float4*)(o)     = f;
        f.x = r2[4].x; f.y = r2[5].x; f.z = r2[6].x; f.w = r2[7].x; *(float4*)(o + 4) = f;
        o += RS; // next row (hi lanes)
        f.x = r2[0].y; f.y = r2[1].y; f.z = r2[2].y; f.w = r2[3].y; *(float4*)(o)     = f;
        f.x = r2[4].y; f.y = r2[5].y; f.z = r2[6].y; f.w = r2[7].y; *(float4*)(o + 4) = f;
    }
}

extern "C" void kernel_launch(void* const* d_in, const int* in_sizes, int n_in,
                              void* d_out, int out_size) {
    const float* Q  = (const float*)d_in[0];
    const float* K  = (const float*)d_in[1];
    const float* V  = (const float*)d_in[2];
    const float* D1 = (const float*)d_in[3];
    float* O = (float*)d_out;

    const int smem2 = (8192 + 8320 + 128 + 64) * 4; // 66816 B > 48KB -> opt-in
    cudaFuncSetAttribute(k_pass2, cudaFuncAttributeMaxDynamicSharedMemorySize, smem2);

    k_pass1 <<<BH * SPLIT, 256>>>(K, V, D1);
    k_reduce<<<BH, 256>>>();
    k_pass2 <<<BH * 32, 256, smem2>>>(Q, O, D1);
}